// round 16
// baseline (speedup 1.0000x reference)
#include <cuda_runtime.h>
#include <math.h>

#define B 32
#define H 512
#define W 512
#define C4 (W / 4)
#define KS 31
#define PAD 15
#define IMG4 (H * C4)
#define STRIPS 32
#define ROWS (H / STRIPS)      // 16
#define RB 4                   // rows per round
#define ROUNDS (ROWS / RB)     // 4
#define NBLOCKS (B * STRIPS)   // 1024

__device__ float g_part[NBLOCKS * 4];
__device__ unsigned int g_ctr;

__inline__ __device__ float warp_reduce(float v) {
    #pragma unroll
    for (int o = 16; o > 0; o >>= 1) v += __shfl_down_sync(0xffffffffu, v, o);
    return v;
}

// four interleaved inclusive warp scans (ILP on the shfl chain)
__inline__ __device__ void warp_iscan4(float& a, float& b, float& c, float& d, int lane) {
    #pragma unroll
    for (int o = 1; o < 32; o <<= 1) {
        const float na = __shfl_up_sync(0xffffffffu, a, o);
        const float nb = __shfl_up_sync(0xffffffffu, b, o);
        const float nc = __shfl_up_sync(0xffffffffu, c, o);
        const float nd = __shfl_up_sync(0xffffffffu, d, o);
        if (lane >= o) { a += na; b += nb; c += nc; d += nd; }
    }
}

__inline__ __device__ float4 f4add(float4 a, float4 b) {
    return make_float4(a.x + b.x, a.y + b.y, a.z + b.z, a.w + b.w);
}
__inline__ __device__ float4 f4sub(float4 a, float4 b) {
    return make_float4(a.x - b.x, a.y - b.y, a.z - b.z, a.w - b.w);
}

__inline__ __device__ float tanh_approx(float x) {
    float r; asm("tanh.approx.f32 %0, %1;" : "=f"(r) : "f"(x)); return r;
}
__inline__ __device__ float fcomp(float4 v, int k) {
    return k == 0 ? v.x : k == 1 ? v.y : k == 2 ? v.z : v.w;
}

template <bool INTERIOR>
__device__ __forceinline__ void run_strip(
    const float4* __restrict__ t, const float4* __restrict__ p,
    int r0, int w, int lane, int wid,
    float4 (*sP)[RB][136], float4 (*s_warp)[4],
    float& acc0, float& acc1, float& acc2, float& acc3)
{
    const float4 zero4 = make_float4(0.f, 0.f, 0.f, 0.f);
    const float invf = 1.0f / (KS * KS);

    // ---- preamble vertical window: rows [r0-15, r0+14] (clamped) ----
    float4 sA = zero4, sB = zero4;
    if (INTERIOR) {
        const float4* tb = t + (r0 - PAD) * C4 + w;
        #pragma unroll
        for (int h = 0; h < 2 * PAD; h += 2) {
            sA = f4add(sA, tb[h * C4]);
            sB = f4add(sB, tb[(h + 1) * C4]);
        }
    } else {
        int hlo = r0 - PAD; if (hlo < 0) hlo = 0;
        int hhi = r0 + PAD; if (hhi > H) hhi = H;
        int h = hlo;
        for (; h + 1 < hhi; h += 2) {
            sA = f4add(sA, t[h * C4 + w]);
            sB = f4add(sB, t[(h + 1) * C4 + w]);
        }
        if (h < hhi) sA = f4add(sA, t[h * C4 + w]);
    }
    float4 sum4 = f4add(sA, sB);

    const float4* tc = t + r0 * C4 + w;
    const float4* pc = p + r0 * C4 + w;

    for (int g = 0; g < ROUNDS; ++g) {
        const int r   = r0 + RB * g;
        const int buf = g & 1;

        // ---- window loads for 4 rows (front-batched) ----
        float4 a[RB], s[RB];
        #pragma unroll
        for (int j = 0; j < RB; ++j) {
            if (INTERIOR) {
                a[j] = tc[(15 + j) * C4];
                s[j] = tc[(j - 15) * C4];
            } else {
                a[j] = (r + j + PAD < H)      ? tc[(15 + j) * C4] : zero4;
                s[j] = (r + j - PAD >= 0)     ? tc[(j - 15) * C4] : zero4;
            }
        }

        // ---- vertical sums + thread-local prefixes for 4 rows ----
        float q[RB][4];
        #pragma unroll
        for (int j = 0; j < RB; ++j) {
            sum4 = f4add(sum4, a[j]);
            q[j][0] = sum4.x;
            q[j][1] = q[j][0] + sum4.y;
            q[j][2] = q[j][1] + sum4.z;
            q[j][3] = q[j][2] + sum4.w;
            sum4 = f4sub(sum4, s[j]);
        }

        // ---- 4-way interleaved warp scan of thread totals ----
        float i0 = q[0][3], i1 = q[1][3], i2 = q[2][3], i3 = q[3][3];
        warp_iscan4(i0, i1, i2, i3, lane);
        const float ex0 = i0 - q[0][3];
        const float ex1 = i1 - q[1][3];
        const float ex2 = i2 - q[2][3];
        const float ex3 = i3 - q[3][3];
        if (lane == 31) s_warp[buf][wid] = make_float4(i0, i1, i2, i3);
        __syncthreads();   // BAR_a

        const float4 W0 = s_warp[buf][0];
        const float4 W1 = s_warp[buf][1];
        const float4 W2 = s_warp[buf][2];
        const float4 W3 = s_warp[buf][3];

        const float ex[RB] = {ex0, ex1, ex2, ex3};
        #pragma unroll
        for (int j = 0; j < RB; ++j) {
            const float w0 = fcomp(W0, j), w1 = fcomp(W1, j), w2 = fcomp(W2, j);
            const float off = (wid > 0 ? w0 : 0.f) + (wid > 1 ? w1 : 0.f)
                            + (wid > 2 ? w2 : 0.f);
            const float base = off + ex[j];
            sP[buf][j][w + 4] = make_float4(base + q[j][0], base + q[j][1],
                                            base + q[j][2], base + q[j][3]);
        }
        if (w < 4 * RB) {
            const int j  = w >> 2;     // row
            const int ix = w & 3;      // pad slot
            const float tot = fcomp(W0, j) + fcomp(W1, j) + fcomp(W2, j) + fcomp(W3, j);
            sP[buf][j][132 + ix] = make_float4(tot, tot, tot, tot);
        }
        __syncthreads();   // BAR_b

        // ---- taps + elementwise loss, row by row ----
        #pragma unroll
        for (int j = 0; j < RB; ++j) {
            const float4 tg = tc[j * C4];
            const float4 xq = pc[j * C4];
            const float4 lo = sP[buf][j][w];
            const float4 A  = sP[buf][j][w + 7];
            const float4 Bv = sP[buf][j][w + 8];

            const float hi[4]  = {A.w, Bv.x, Bv.y, Bv.z};
            const float lov[4] = {lo.x, lo.y, lo.z, lo.w};
            const float tgv[4] = {tg.x, tg.y, tg.z, tg.w};
            const float xv[4]  = {xq.x, xq.y, xq.z, xq.w};

            #pragma unroll
            for (int k = 0; k < 4; ++k) {
                const float box  = (hi[k] - lov[k]) * invf;
                const float weit = fmaf(5.f, fabsf(box - tgv[k]), 1.f);

                // p = 0.5*tanh(x/2)+0.5 (MUFU.TANH); bce = x*(1-t) - log(p)
                const float ph  = tanh_approx(0.5f * xv[k]);
                const float pr  = fmaf(0.5f, ph, 0.5f);
                const float lg  = __logf(pr);
                const float bce = fmaf(xv[k], 1.f - tgv[k], -lg);

                acc0 += weit;
                acc1 = fmaf(weit, bce, acc1);
                acc2 = fmaf(pr * tgv[k], weit, acc2);
                acc3 = fmaf(pr + tgv[k], weit, acc3);
            }
        }

        tc += RB * C4;
        pc += RB * C4;
    }
}

__global__ void __launch_bounds__(128, 7)
fused_loss_kernel(const float4* __restrict__ pred,
                  const float4* __restrict__ target,
                  float* __restrict__ out) {
    const int strip = blockIdx.x;
    const int b     = blockIdx.y;
    const int w     = threadIdx.x;
    const int lane  = w & 31;
    const int wid   = w >> 5;
    const int r0    = strip * ROWS;

    const float4* t = target + b * IMG4;
    const float4* p = pred   + b * IMG4;

    __shared__ float4 sP[2][RB][136];
    __shared__ float4 s_warp[2][4];
    __shared__ float  s_red[4][4];

    // zero the front pads of all buffers/rows: 2*RB*4 = 32 entries
    if (w < 2 * RB * 4) {
        sP[w >> 4][(w >> 2) & (RB - 1)][w & 3] = make_float4(0.f, 0.f, 0.f, 0.f);
    }

    float acc0 = 0.f, acc1 = 0.f, acc2 = 0.f, acc3 = 0.f;

    if (strip >= 1 && strip <= STRIPS - 2) {
        run_strip<true>(t, p, r0, w, lane, wid, sP, s_warp, acc0, acc1, acc2, acc3);
    } else {
        run_strip<false>(t, p, r0, w, lane, wid, sP, s_warp, acc0, acc1, acc2, acc3);
    }

    // ---- block reduction (4 warps) ----
    float vals[4] = {acc0, acc1, acc2, acc3};
    #pragma unroll
    for (int k = 0; k < 4; ++k) {
        const float v = warp_reduce(vals[k]);
        if (lane == 0) s_red[k][wid] = v;
    }
    __syncthreads();

    if (wid == 0) {
        float v[4];
        #pragma unroll
        for (int k = 0; k < 4; ++k) {
            float vv = (lane < 4) ? s_red[k][lane] : 0.f;
            #pragma unroll
            for (int o = 2; o > 0; o >>= 1) vv += __shfl_down_sync(0xffffffffu, vv, o);
            v[k] = vv;
        }
        if (lane == 0) {
            #pragma unroll
            for (int k = 0; k < 4; ++k)
                g_part[(b * STRIPS + strip) * 4 + k] = v[k];
            __threadfence();
        }
        __syncwarp();

        unsigned int ticket = 0;
        if (lane == 0) ticket = atomicAdd(&g_ctr, 1u);
        ticket = __shfl_sync(0xffffffffu, ticket, 0);
        if (ticket == NBLOCKS - 1) {
            float wsum = 0.f, wbce_n = 0.f, inter = 0.f, uni = 0.f;
            #pragma unroll 4
            for (int s = 0; s < STRIPS; ++s) {
                const float* pp = &g_part[(lane * STRIPS + s) * 4];
                wsum   += pp[0];
                wbce_n += pp[1];
                inter  += pp[2];
                uni    += pp[3];
            }
            const float wbce = wbce_n / wsum;
            const float wiou = 1.0f - (inter + 1.0f) / (uni - inter + 1.0f);
            float loss = warp_reduce(wbce + wiou);
            if (lane == 0) {
                out[0] = loss * (1.0f / B);
                g_ctr = 0;
            }
        }
    }
}

extern "C" void kernel_launch(void* const* d_in, const int* in_sizes, int n_in,
                              void* d_out, int out_size) {
    const float4* pred   = (const float4*)d_in[0];
    const float4* target = (const float4*)d_in[1];
    float* out = (float*)d_out;

    dim3 grid(STRIPS, B);
    fused_loss_kernel<<<grid, 128>>>(pred, target, out);
}

// round 17
// speedup vs baseline: 1.1015x; 1.1015x over previous
#include <cuda_runtime.h>
#include <math.h>

#define B 32
#define H 512
#define W 512
#define C4 (W / 4)
#define KS 31
#define PAD 15
#define IMG4 (H * C4)
#define STRIPS 37              // 36 strips of 14 rows + 1 strip of 8 rows
#define SROWS 14
#define NBLOCKS (B * STRIPS)   // 1184 = 148 * 8 : exactly 8 CTAs/SM, one wave

__device__ float g_part[NBLOCKS * 4];
__device__ unsigned int g_ctr;

__inline__ __device__ float warp_reduce(float v) {
    #pragma unroll
    for (int o = 16; o > 0; o >>= 1) v += __shfl_down_sync(0xffffffffu, v, o);
    return v;
}

__inline__ __device__ void warp_iscan2(float& a, float& b, int lane) {
    #pragma unroll
    for (int o = 1; o < 32; o <<= 1) {
        const float na = __shfl_up_sync(0xffffffffu, a, o);
        const float nb = __shfl_up_sync(0xffffffffu, b, o);
        if (lane >= o) { a += na; b += nb; }
    }
}

__inline__ __device__ float4 f4add(float4 a, float4 b) {
    return make_float4(a.x + b.x, a.y + b.y, a.z + b.z, a.w + b.w);
}
__inline__ __device__ float4 f4sub(float4 a, float4 b) {
    return make_float4(a.x - b.x, a.y - b.y, a.z - b.z, a.w - b.w);
}

__inline__ __device__ float tanh_approx(float x) {
    float r; asm("tanh.approx.f32 %0, %1;" : "=f"(r) : "f"(x)); return r;
}

template <bool INTERIOR>
__device__ __forceinline__ void run_strip(
    const float4* __restrict__ t, const float4* __restrict__ p,
    int r0, int nrounds, int w, int lane, int wid,
    float4 (*sP)[2][136], float2 (*s_warp)[4],
    float& acc0, float& acc1, float& acc2, float& acc3)
{
    const float4 zero4 = make_float4(0.f, 0.f, 0.f, 0.f);
    const float invf = 1.0f / (KS * KS);

    // ---- preamble vertical window: rows [r0-15, r0+14] (clamped) ----
    float4 sA = zero4, sB = zero4;
    if (INTERIOR) {
        const float4* tb = t + (r0 - PAD) * C4 + w;
        #pragma unroll
        for (int h = 0; h < 2 * PAD; h += 2) {
            sA = f4add(sA, tb[h * C4]);
            sB = f4add(sB, tb[(h + 1) * C4]);
        }
    } else {
        int hlo = r0 - PAD; if (hlo < 0) hlo = 0;
        int hhi = r0 + PAD; if (hhi > H) hhi = H;
        int h = hlo;
        for (; h + 1 < hhi; h += 2) {
            sA = f4add(sA, t[h * C4 + w]);
            sB = f4add(sB, t[(h + 1) * C4 + w]);
        }
        if (h < hhi) sA = f4add(sA, t[h * C4 + w]);
    }
    float4 sum4 = f4add(sA, sB);

    const float4* tc = t + r0 * C4 + w;
    const float4* pc = p + r0 * C4 + w;

    for (int g = 0; g < nrounds; ++g) {
        const int r   = r0 + 2 * g;
        const int buf = g & 1;

        float4 a0, a1, s0, s1;
        if (INTERIOR) {
            a0 = tc[15 * C4];
            a1 = tc[16 * C4];
            s0 = tc[-15 * C4];
            s1 = tc[-14 * C4];
        } else {
            a0 = (r + PAD < H)      ? tc[15 * C4]  : zero4;
            a1 = (r + 1 + PAD < H)  ? tc[16 * C4]  : zero4;
            s0 = (r - PAD >= 0)     ? tc[-15 * C4] : zero4;
            s1 = (r + 1 - PAD >= 0) ? tc[-14 * C4] : zero4;
        }

        sum4 = f4add(sum4, a0);
        const float4 vs0 = sum4;
        sum4 = f4sub(sum4, s0);
        sum4 = f4add(sum4, a1);
        const float4 vs1 = sum4;
        sum4 = f4sub(sum4, s1);

        const float q0a = vs0.x, q1a = q0a + vs0.y, q2a = q1a + vs0.z, q3a = q2a + vs0.w;
        const float q0b = vs1.x, q1b = q0b + vs1.y, q2b = q1b + vs1.z, q3b = q2b + vs1.w;

        float ia = q3a, ib = q3b;
        warp_iscan2(ia, ib, lane);
        const float exa = ia - q3a;
        const float exb = ib - q3b;
        if (lane == 31) s_warp[buf][wid] = make_float2(ia, ib);
        __syncthreads();   // BAR_a

        const float2 W0 = s_warp[buf][0];
        const float2 W1 = s_warp[buf][1];
        const float2 W2 = s_warp[buf][2];
        const float2 W3 = s_warp[buf][3];

        const float offa = (wid > 0 ? W0.x : 0.f) + (wid > 1 ? W1.x : 0.f) + (wid > 2 ? W2.x : 0.f);
        const float offb = (wid > 0 ? W0.y : 0.f) + (wid > 1 ? W1.y : 0.f) + (wid > 2 ? W2.y : 0.f);
        const float basea = offa + exa;
        const float baseb = offb + exb;

        sP[buf][0][w + 4] = make_float4(basea + q0a, basea + q1a, basea + q2a, basea + q3a);
        sP[buf][1][w + 4] = make_float4(baseb + q0b, baseb + q1b, baseb + q2b, baseb + q3b);
        if (w < 4) {
            const float tota = W0.x + W1.x + W2.x + W3.x;
            const float totb = W0.y + W1.y + W2.y + W3.y;
            sP[buf][0][132 + w] = make_float4(tota, tota, tota, tota);
            sP[buf][1][132 + w] = make_float4(totb, totb, totb, totb);
        }
        __syncthreads();   // BAR_b

        #pragma unroll
        for (int j = 0; j < 2; ++j) {
            const float4 tg = j ? tc[C4] : tc[0];
            const float4 xq = j ? pc[C4] : pc[0];
            const float4 lo = sP[buf][j][w];
            const float4 A  = sP[buf][j][w + 7];
            const float4 Bv = sP[buf][j][w + 8];

            const float hi[4]  = {A.w, Bv.x, Bv.y, Bv.z};
            const float lov[4] = {lo.x, lo.y, lo.z, lo.w};
            const float tgv[4] = {tg.x, tg.y, tg.z, tg.w};
            const float xv[4]  = {xq.x, xq.y, xq.z, xq.w};

            #pragma unroll
            for (int k = 0; k < 4; ++k) {
                const float box  = (hi[k] - lov[k]) * invf;
                const float weit = fmaf(5.f, fabsf(box - tgv[k]), 1.f);

                // p = 0.5*tanh(x/2)+0.5 (MUFU.TANH); bce = x*(1-t) - log(p)
                const float ph  = tanh_approx(0.5f * xv[k]);
                const float pr  = fmaf(0.5f, ph, 0.5f);
                const float lg  = __logf(pr);
                const float bce = fmaf(xv[k], 1.f - tgv[k], -lg);

                acc0 += weit;
                acc1 = fmaf(weit, bce, acc1);
                acc2 = fmaf(pr * tgv[k], weit, acc2);
                acc3 = fmaf(pr + tgv[k], weit, acc3);
            }
        }

        tc += 2 * C4;
        pc += 2 * C4;
    }
}

__global__ void __launch_bounds__(128, 8)
fused_loss_kernel(const float4* __restrict__ pred,
                  const float4* __restrict__ target,
                  float* __restrict__ out) {
    const int strip = blockIdx.x;   // 0..36
    const int b     = blockIdx.y;
    const int w     = threadIdx.x;
    const int lane  = w & 31;
    const int wid   = w >> 5;
    const int r0    = strip * SROWS;                 // strip 36 -> 504
    const int nrounds = (strip == STRIPS - 1) ? 4 : 7;  // 8 or 14 rows

    const float4* t = target + b * IMG4;
    const float4* p = pred   + b * IMG4;

    __shared__ float4 sP[2][2][136];
    __shared__ float2 s_warp[2][4];
    __shared__ float  s_red[4][4];

    if (w < 16) sP[(w >> 3) & 1][(w >> 2) & 1][w & 3] = make_float4(0.f, 0.f, 0.f, 0.f);

    float acc0 = 0.f, acc1 = 0.f, acc2 = 0.f, acc3 = 0.f;

    // interior: r0-15 >= 0 and deepest window row r0+13+16 <= 511
    const int rows = nrounds * 2;
    if (r0 - PAD >= 0 && r0 + rows - 1 + PAD + 1 <= H - 1) {
        run_strip<true>(t, p, r0, nrounds, w, lane, wid, sP, s_warp, acc0, acc1, acc2, acc3);
    } else {
        run_strip<false>(t, p, r0, nrounds, w, lane, wid, sP, s_warp, acc0, acc1, acc2, acc3);
    }

    // ---- block reduction (4 warps) ----
    float vals[4] = {acc0, acc1, acc2, acc3};
    #pragma unroll
    for (int k = 0; k < 4; ++k) {
        const float v = warp_reduce(vals[k]);
        if (lane == 0) s_red[k][wid] = v;
    }
    __syncthreads();

    if (wid == 0) {
        float v[4];
        #pragma unroll
        for (int k = 0; k < 4; ++k) {
            float vv = (lane < 4) ? s_red[k][lane] : 0.f;
            #pragma unroll
            for (int o = 2; o > 0; o >>= 1) vv += __shfl_down_sync(0xffffffffu, vv, o);
            v[k] = vv;
        }
        if (lane == 0) {
            #pragma unroll
            for (int k = 0; k < 4; ++k)
                g_part[(b * STRIPS + strip) * 4 + k] = v[k];
            __threadfence();
        }
        __syncwarp();

        unsigned int ticket = 0;
        if (lane == 0) ticket = atomicAdd(&g_ctr, 1u);
        ticket = __shfl_sync(0xffffffffu, ticket, 0);
        if (ticket == NBLOCKS - 1) {
            float wsum = 0.f, wbce_n = 0.f, inter = 0.f, uni = 0.f;
            for (int s = 0; s < STRIPS; ++s) {
                const float* pp = &g_part[(lane * STRIPS + s) * 4];
                wsum   += pp[0];
                wbce_n += pp[1];
                inter  += pp[2];
                uni    += pp[3];
            }
            const float wbce = wbce_n / wsum;
            const float wiou = 1.0f - (inter + 1.0f) / (uni - inter + 1.0f);
            float loss = warp_reduce(wbce + wiou);
            if (lane == 0) {
                out[0] = loss * (1.0f / B);
                g_ctr = 0;
            }
        }
    }
}

extern "C" void kernel_launch(void* const* d_in, const int* in_sizes, int n_in,
                              void* d_out, int out_size) {
    const float4* pred   = (const float4*)d_in[0];
    const float4* target = (const float4*)d_in[1];
    float* out = (float*)d_out;

    dim3 grid(STRIPS, B);
    fused_loss_kernel<<<grid, 128>>>(pred, target, out);
}